// round 5
// baseline (speedup 1.0000x reference)
#include <cuda_runtime.h>
#include <cstdint>
#include <cstddef>

#define B_   32
#define T_   512
#define KIN  1024
#define H_   1024
#define G_   4096          // 4*H
#define M_   (B_*T_)       // 16384
#define JT   8             // j-units per block
#define NBLK 128           // persistent grid
#define NTHR 512           // threads per persistent block (16 warps)
#define BG   16            // batches per group (2 groups)

// Scratch (device globals: allocation-free per harness rules)
__device__ float g_xproj[(size_t)M_ * G_];   // 256 MB: x@W_ih^T + b_ih
__device__ float g_h[2][B_*H_];              // double-buffered hidden state

// split-barrier counters: [group][tag mod 8], zeroed each launch
__device__ unsigned g_cntr[2][8];

typedef unsigned long long u64;

// sm_103a packed fp32 FMA (2 MACs/issue; ptxas won't auto-fuse — PTX only)
__device__ __forceinline__ void fma2(u64 &d, u64 a, u64 b){
    asm("fma.rn.f32x2 %0, %1, %2, %0;" : "+l"(d) : "l"(a), "l"(b));
}
__device__ __forceinline__ u64 pack2(float lo, float hi){
    u64 r; asm("mov.b64 %0, {%1,%2};" : "=l"(r) : "f"(lo), "f"(hi)); return r;
}
__device__ __forceinline__ float2 unpack2(u64 v){
    float2 f; asm("mov.b64 {%0,%1}, %2;" : "=f"(f.x), "=f"(f.y) : "l"(v)); return f;
}

// ------------------------------------------------------------------
// Phase 1: g_xproj[m][n] = sum_k inputs[m][k]*W_ih[n][k] + b_ih[n]
// (unchanged — ~2.5 ms)
// ------------------------------------------------------------------
#define P1_BM 64
#define P1_BN 64
#define P1_BK 16

__global__ void __launch_bounds__(256, 2) xproj_kernel(
    const float* __restrict__ A,
    const float* __restrict__ W,
    const float* __restrict__ bias)
{
    __shared__ __align__(16) u64   As2[P1_BK][P1_BM + 1];
    __shared__ __align__(16) float Bst[P1_BK][P1_BN + 2];

    const int tid = threadIdx.x;
    const int m0 = blockIdx.y * P1_BM;
    const int n0 = blockIdx.x * P1_BN;
    const int tx = tid & 15;
    const int ty = tid >> 4;
    const int lrow = tid >> 2;
    const int lk   = (tid & 3) * 4;

    u64 acc[4][2];
    #pragma unroll
    for (int i = 0; i < 4; i++) { acc[i][0] = 0ULL; acc[i][1] = 0ULL; }

    const float* Arow = A + (size_t)(m0 + lrow) * KIN + lk;
    const float* Wrow = W + (size_t)(n0 + lrow) * KIN + lk;

    for (int kc = 0; kc < KIN; kc += P1_BK) {
        float4 av = *(const float4*)(Arow + kc);
        float4 wv = *(const float4*)(Wrow + kc);
        As2[lk+0][lrow] = pack2(av.x, av.x);
        As2[lk+1][lrow] = pack2(av.y, av.y);
        As2[lk+2][lrow] = pack2(av.z, av.z);
        As2[lk+3][lrow] = pack2(av.w, av.w);
        Bst[lk+0][lrow] = wv.x;
        Bst[lk+1][lrow] = wv.y;
        Bst[lk+2][lrow] = wv.z;
        Bst[lk+3][lrow] = wv.w;
        __syncthreads();

        #pragma unroll
        for (int k = 0; k < P1_BK; k++) {
            u64 a0 = As2[k][ty*4+0];
            u64 a1 = As2[k][ty*4+1];
            u64 a2 = As2[k][ty*4+2];
            u64 a3 = As2[k][ty*4+3];
            u64 b0 = *(const u64*)&Bst[k][tx*4];
            u64 b1 = *(const u64*)&Bst[k][tx*4+2];
            fma2(acc[0][0], a0, b0); fma2(acc[0][1], a0, b1);
            fma2(acc[1][0], a1, b0); fma2(acc[1][1], a1, b1);
            fma2(acc[2][0], a2, b0); fma2(acc[2][1], a2, b1);
            fma2(acc[3][0], a3, b0); fma2(acc[3][1], a3, b1);
        }
        __syncthreads();
    }

    #pragma unroll
    for (int i = 0; i < 4; i++) {
        int m = m0 + ty*4 + i;
        float* crow = g_xproj + (size_t)m * G_ + n0 + tx*4;
        #pragma unroll
        for (int j = 0; j < 2; j++) {
            float2 v = unpack2(acc[i][j]);
            int n = n0 + tx*4 + 2*j;
            crow[2*j]   = v.x + bias[n];
            crow[2*j+1] = v.y + bias[n+1];
        }
    }
}

// ------------------------------------------------------------------
// Phase 2: persistent LSTM scan, 128 blocks x 512 threads.
// Two independent batch groups (0-15, 16-31) alternate; split
// arrive/wait counters hide barrier + h-visibility latency behind
// the other group's compute.
// ------------------------------------------------------------------

// wait until all 128 blocks arrived tag t for group g.
// arrive tags run 1..511; slot s=t&7 has received exactly
// ((t+7)>>3) full rounds by the time tag t is complete.
__device__ __forceinline__ void scan_wait(int g, int t)
{
    if (threadIdx.x == 0) {
        unsigned tgt = 128u * ((unsigned)(t + 7) >> 3);
        volatile unsigned* p = &g_cntr[g][t & 7];
        while (*p < tgt) { }
        __threadfence();
    }
    __syncthreads();
}
// signal this block finished writing h[tag t] for group g
__device__ __forceinline__ void scan_arrive(int g, int t)
{
    __syncthreads();
    if (threadIdx.x == 0) {
        __threadfence();
        atomicAdd(&g_cntr[g][t & 7], 1u);
    }
}

__global__ void reset_barrier()
{
    if (threadIdx.x < 16) ((unsigned*)g_cntr)[threadIdx.x] = 0u;
}

// dynamic smem layout (floats)
#define HP          1028                 // hs row pitch (16B-aligned rows)
#define HS_FLOATS   (32*HP)
#define PB_STRIDE   (32*17)              // per-warp partials: [c][bl]
#define PB_FLOATS   (16*PB_STRIDE)
#define SP_FLOATS   (32*17)
#define SMEM_BYTES  ((HS_FLOATS + PB_FLOATS + SP_FLOATS)*4)

extern __shared__ float smemf[];

__global__ void __launch_bounds__(NTHR, 1) lstm_persistent(
    const float* __restrict__ h0,
    const float* __restrict__ c0,
    const float* __restrict__ Whh,
    const float* __restrict__ bhh,
    float* __restrict__ out)
{
    float* hs   = smemf;                 // [32][HP]
    float* pbuf = smemf + HS_FLOATS;     // [16][32][17]
    float* sp   = pbuf + PB_FLOATS;      // [32][17]

    const int tid = threadIdx.x;
    const int jb  = blockIdx.x;
    const int w   = tid >> 5;            // warp 0..15 (k-slice)
    const int c   = tid & 31;            // column 0..31 (gate*8 + jj)
    const int n_c = (c >> 3)*H_ + jb*JT + (c & 7);

    // --- W slice in registers for all 512 steps: 32 u64 (64 regs) ---
    u64 wreg[32];
    {
        const float4* wp = (const float4*)(Whh + (size_t)n_c*KIN + w*64);
        #pragma unroll
        for (int m = 0; m < 16; m++) {
            float4 v = wp[m];
            wreg[2*m]   = pack2(v.x, v.y);
            wreg[2*m+1] = pack2(v.z, v.w);
        }
    }

    // --- cell-update mapping: threads 0..127 -> (b_local, jj) ---
    const bool upd = (tid < 128);
    const int ub = (tid >> 3) & 15;      // local batch 0..15
    const int uj = tid & 7;
    const int jg = jb*JT + uj;

    float bh0=0.f, bh1=0.f, bh2=0.f, bh3=0.f;
    float cs[2] = {0.f, 0.f};            // cell state per group
    if (upd) {
        bh0 = bhh[0*H_ + jg];
        bh1 = bhh[1*H_ + jg];
        bh2 = bhh[2*H_ + jg];
        bh3 = bhh[3*H_ + jg];
        cs[0] = c0[(0*BG + ub)*H_ + jg];
        cs[1] = c0[(1*BG + ub)*H_ + jg];
    }

    const size_t OFF_H = (size_t)B_*T_*H_;
    const size_t OFF_C = OFF_H + (size_t)B_*H_;

    for (int t = 0; t < T_; t++) {
        const float* hprev = (t == 0) ? h0 : g_h[t & 1];
        float*       hnext = g_h[(t + 1) & 1];

        #pragma unroll
        for (int g = 0; g < 2; g++) {
            const int b0 = g * BG;

            // wait for this group's h_t to be globally visible
            if (t > 0) scan_wait(g, t);

            // xproj prefetch (lands during staging+mainloop)
            float xp0=0.f, xp1=0.f, xp2=0.f, xp3=0.f;
            if (upd) {
                const float* xrow =
                    g_xproj + ((size_t)(b0 + ub)*T_ + t)*G_ + jg;
                xp0 = xrow[0*H_]; xp1 = xrow[1*H_];
                xp2 = xrow[2*H_]; xp3 = xrow[3*H_];
            }

            // stage group h: 16 rows x 1024 fl = 4096 float4
            {
                const float4* hsrc = (const float4*)hprev;
                #pragma unroll
                for (int it = 0; it < 8; it++) {
                    int e = tid + NTHR*it;         // 0..4095
                    int r = e >> 8, col4 = e & 255;
                    *(float4*)(hs + (b0 + r)*HP + col4*4) =
                        hsrc[(b0 + r)*256 + col4];
                }
            }
            __syncthreads();

            // mainloop: per b, 16 broadcast LDS.128 + 32 fma2
            {
                float* prow = pbuf + w*PB_STRIDE + c*17;
                #pragma unroll 2
                for (int bl = 0; bl < BG; bl++) {
                    const ulonglong2* hb =
                        (const ulonglong2*)(hs + (b0 + bl)*HP + w*64);
                    u64 a0 = 0ULL, a1 = 0ULL;
                    #pragma unroll
                    for (int m = 0; m < 16; m++) {
                        ulonglong2 hv = hb[m];
                        fma2(a0, wreg[2*m],   hv.x);
                        fma2(a1, wreg[2*m+1], hv.y);
                    }
                    float2 f0 = unpack2(a0), f1 = unpack2(a1);
                    prow[bl] = (f0.x + f0.y) + (f1.x + f1.y);
                }
            }
            __syncthreads();

            // reduce 16 warp partials: thread -> (cc, bl)
            {
                int cc = tid >> 4, bl = tid & 15;
                float s = 0.f;
                #pragma unroll
                for (int ww = 0; ww < 16; ww++)
                    s += pbuf[ww*PB_STRIDE + cc*17 + bl];
                sp[cc*17 + bl] = s;
            }
            __syncthreads();

            // gates + cell update
            if (upd) {
                float p0 = sp[(0*8 + uj)*17 + ub] + xp0 + bh0;
                float p1 = sp[(1*8 + uj)*17 + ub] + xp1 + bh1;
                float p2 = sp[(2*8 + uj)*17 + ub] + xp2 + bh2;
                float p3 = sp[(3*8 + uj)*17 + ub] + xp3 + bh3;

                float ig = 1.f / (1.f + __expf(-p0));
                float fg = 1.f / (1.f + __expf(-p1));
                float og = 1.f / (1.f + __expf(-p2));
                float gg = tanhf(p3);
                float cn = cs[g]*fg + ig*gg;
                cs[g] = cn;
                float hn = og * tanhf(cn);

                int b = b0 + ub;
                hnext[b*H_ + jg] = hn;
                out[((size_t)b*T_ + t)*H_ + jg] = hn;
                if (t == T_ - 1) {
                    out[OFF_H + (size_t)b*H_ + jg] = hn;
                    out[OFF_C + (size_t)b*H_ + jg] = cn;
                }
            }

            // publish h[t+1] for this group (hidden behind other group)
            if (t + 1 < T_) scan_arrive(g, t + 1);
            else            __syncthreads();
        }
    }
}

extern "C" void kernel_launch(void* const* d_in, const int* in_sizes, int n_in,
                              void* d_out, int out_size)
{
    (void)in_sizes; (void)n_in; (void)out_size;
    const float* inputs = (const float*)d_in[0];
    const float* h0     = (const float*)d_in[1];
    const float* c0     = (const float*)d_in[2];
    const float* Wih    = (const float*)d_in[3];
    const float* bih    = (const float*)d_in[4];
    const float* Whh    = (const float*)d_in[5];
    const float* bhh    = (const float*)d_in[6];
    float* out = (float*)d_out;

    cudaFuncSetAttribute(lstm_persistent,
                         cudaFuncAttributeMaxDynamicSharedMemorySize,
                         SMEM_BYTES);

    reset_barrier<<<1, 32>>>();
    xproj_kernel<<<dim3(G_/P1_BN, M_/P1_BM), 256>>>(inputs, Wih, bih);
    lstm_persistent<<<NBLK, NTHR, SMEM_BYTES>>>(h0, c0, Whh, bhh, out);
}

// round 6
// speedup vs baseline: 1.0534x; 1.0534x over previous
#include <cuda_runtime.h>
#include <cstdint>
#include <cstddef>

#define B_   32
#define T_   512
#define KIN  1024
#define H_   1024
#define G_   4096          // 4*H
#define M_   (B_*T_)       // 16384
#define JT   8             // j-units per block
#define NBLK 128           // persistent grid
#define NTHR 512           // 16 warps

// Scratch (device globals: allocation-free per harness rules)
__device__ float g_xproj[(size_t)M_ * G_];   // 256 MB: x@W_ih^T + b_ih
__device__ float g_h[2][B_*H_];              // double-buffered hidden state

// tree barrier: 8 slots, 128 B apart (distinct LTS slices).
// Zeroed by block 0 at kernel start (first use is ~2.6 ms later).
__device__ unsigned g_arr[8*32];

typedef unsigned long long u64;

// sm_103a packed fp32 FMA (2 MACs/issue; PTX-only, ptxas won't auto-fuse)
__device__ __forceinline__ void fma2(u64 &d, u64 a, u64 b){
    asm("fma.rn.f32x2 %0, %1, %2, %0;" : "+l"(d) : "l"(a), "l"(b));
}
__device__ __forceinline__ u64 pack2(float lo, float hi){
    u64 r; asm("mov.b64 %0, {%1,%2};" : "=l"(r) : "f"(lo), "f"(hi)); return r;
}
__device__ __forceinline__ float2 unpack2(u64 v){
    float2 f; asm("mov.b64 {%0,%1}, %2;" : "=f"(f.x), "=f"(f.y) : "l"(v)); return f;
}

// grid sync, epoch e = 1,2,3,... ; 16 arrivals per slot per epoch
__device__ __forceinline__ void grid_sync(int jb, unsigned e)
{
    __syncthreads();
    if (threadIdx.x == 0) {
        __threadfence();
        atomicAdd(&g_arr[(jb & 7) * 32], 1u);
        unsigned tgt = 16u * e;
        volatile unsigned* a = g_arr;
        for (;;) {
            unsigned v0 = a[0*32], v1 = a[1*32], v2 = a[2*32], v3 = a[3*32];
            unsigned v4 = a[4*32], v5 = a[5*32], v6 = a[6*32], v7 = a[7*32];
            if (v0>=tgt && v1>=tgt && v2>=tgt && v3>=tgt &&
                v4>=tgt && v5>=tgt && v6>=tgt && v7>=tgt) break;
        }
        __threadfence();
    }
    __syncthreads();
}

// ------------------------------------------------------------------
// dynamic smem: scan layout (xproj phase aliases the same region)
//   hs  : [32][HP]       staged h
//   pbuf: [16][32][33]   per-warp partials
//   sp  : [32][33]       reduced preacts
// ------------------------------------------------------------------
#define HP          1028
#define HS_FLOATS   (32*HP)
#define PB_STRIDE   (32*33)
#define PB_FLOATS   (16*PB_STRIDE)
#define SP_FLOATS   (32*33)
#define SMEM_BYTES  ((HS_FLOATS + PB_FLOATS + SP_FLOATS)*4)

// xproj-phase aliases (fit easily inside the scan region)
// As2: u64 [16][66]  (16B-aligned rows), Bst: float [16][132]
#define XP_AS2_U64   (16*66)
#define XP_BST_OFF   (XP_AS2_U64*2)          // in floats

extern __shared__ float smemf[];

__global__ void __launch_bounds__(NTHR, 1) lstm_fused(
    const float* __restrict__ A,      // inputs [M_][KIN]
    const float* __restrict__ h0,
    const float* __restrict__ c0,
    const float* __restrict__ Wih,    // [G_][KIN]
    const float* __restrict__ bih,
    const float* __restrict__ Whh,    // [G_][KIN]
    const float* __restrict__ bhh,
    float* __restrict__ out)
{
    const int tid = threadIdx.x;
    const int jb  = blockIdx.x;

    // reset barrier counters (first grid_sync is ~2.6 ms away)
    if (jb == 0 && tid < 8) g_arr[tid*32] = 0u;
    if (jb == 0 && tid < 8) __threadfence();

    unsigned epoch = 0;

    // ==============================================================
    // Phase A: xproj. 64m x 128n tiles, BK=16; 64 tiles per block.
    // ==============================================================
    {
        u64*   As2 = (u64*)smemf;                 // [16][66]
        float* Bst = smemf + XP_BST_OFF;          // [16][132]

        const int tx = tid & 31;                  // n: tx*4
        const int ty = tid >> 5;                  // m: ty*4 (== warp id)
        const int wrow = tid >> 2;                // W loader row 0..127
        const int wk   = (tid & 3) * 4;
        const int lrow = (tid & 255) >> 2;        // A loader row 0..63
        const int lk   = (tid & 3) * 4;

        for (int i6 = 0; i6 < 64; i6++) {
            int tt = jb*64 + i6;
            int m0 = (tt >> 5) * 64;
            int n0 = (tt & 31) * 128;

            u64 acc[4][2];
            #pragma unroll
            for (int i = 0; i < 4; i++) { acc[i][0]=0ULL; acc[i][1]=0ULL; }

            const float* Arow = A   + (size_t)(m0 + lrow)*KIN + lk;
            const float* Wrow = Wih + (size_t)(n0 + wrow)*KIN + wk;

            for (int kc = 0; kc < KIN; kc += 16) {
                if (tid < 256) {
                    float4 av = *(const float4*)(Arow + kc);
                    As2[(lk+0)*66 + lrow] = pack2(av.x, av.x);
                    As2[(lk+1)*66 + lrow] = pack2(av.y, av.y);
                    As2[(lk+2)*66 + lrow] = pack2(av.z, av.z);
                    As2[(lk+3)*66 + lrow] = pack2(av.w, av.w);
                }
                float4 wv = *(const float4*)(Wrow + kc);
                Bst[(wk+0)*132 + wrow] = wv.x;
                Bst[(wk+1)*132 + wrow] = wv.y;
                Bst[(wk+2)*132 + wrow] = wv.z;
                Bst[(wk+3)*132 + wrow] = wv.w;
                __syncthreads();

                #pragma unroll
                for (int k = 0; k < 16; k++) {
                    const ulonglong2* ap =
                        (const ulonglong2*)&As2[k*66 + ty*4];
                    ulonglong2 a01 = ap[0];
                    ulonglong2 a23 = ap[1];
                    u64 b0 = *(const u64*)&Bst[k*132 + tx*4];
                    u64 b1 = *(const u64*)&Bst[k*132 + tx*4 + 2];
                    fma2(acc[0][0], a01.x, b0); fma2(acc[0][1], a01.x, b1);
                    fma2(acc[1][0], a01.y, b0); fma2(acc[1][1], a01.y, b1);
                    fma2(acc[2][0], a23.x, b0); fma2(acc[2][1], a23.x, b1);
                    fma2(acc[3][0], a23.y, b0); fma2(acc[3][1], a23.y, b1);
                }
                __syncthreads();
            }

            float bn0 = bih[n0 + tx*4];
            float bn1 = bih[n0 + tx*4 + 1];
            float bn2 = bih[n0 + tx*4 + 2];
            float bn3 = bih[n0 + tx*4 + 3];
            #pragma unroll
            for (int i = 0; i < 4; i++) {
                int m = m0 + ty*4 + i;
                float* crow = g_xproj + (size_t)m*G_ + n0 + tx*4;
                float2 v0 = unpack2(acc[i][0]);
                float2 v1 = unpack2(acc[i][1]);
                crow[0] = v0.x + bn0;
                crow[1] = v0.y + bn1;
                crow[2] = v1.x + bn2;
                crow[3] = v1.y + bn3;
            }
        }
    }

    grid_sync(jb, ++epoch);   // xproj complete everywhere

    // ==============================================================
    // Phase B: recurrent scan (round-3 monolithic structure)
    // ==============================================================
    float* hs   = smemf;                 // [32][HP]
    float* pbuf = smemf + HS_FLOATS;     // [16][32][33]
    float* sp   = pbuf + PB_FLOATS;      // [32][33]

    const int w   = tid >> 5;            // warp 0..15 (k-slice)
    const int c   = tid & 31;            // column (gate*8 + jj)
    const int n_c = (c >> 3)*H_ + jb*JT + (c & 7);

    // W_hh slice in registers for all 512 steps (32 u64 = 64 regs)
    u64 wreg[32];
    {
        const float4* wp = (const float4*)(Whh + (size_t)n_c*KIN + w*64);
        #pragma unroll
        for (int m = 0; m < 16; m++) {
            float4 v = wp[m];
            wreg[2*m]   = pack2(v.x, v.y);
            wreg[2*m+1] = pack2(v.z, v.w);
        }
    }

    const bool upd = (tid < 256);
    const int ub = tid >> 3;             // batch 0..31 (for tid<256)
    const int uj = tid & 7;
    const int jg = jb*JT + uj;

    float bh0=0.f, bh1=0.f, bh2=0.f, bh3=0.f, cstate=0.f;
    if (upd) {
        bh0 = bhh[0*H_ + jg];
        bh1 = bhh[1*H_ + jg];
        bh2 = bhh[2*H_ + jg];
        bh3 = bhh[3*H_ + jg];
        cstate = c0[ub*H_ + jg];
    }

    const size_t OFF_H = (size_t)B_*T_*H_;
    const size_t OFF_C = OFF_H + (size_t)B_*H_;

    for (int t = 0; t < T_; t++) {
        const float* hprev = (t == 0) ? h0 : g_h[t & 1];
        float*       hnext = g_h[(t + 1) & 1];

        // xproj prefetch was issued BEFORE the barrier (end of prev iter);
        // at t==0 issue it here.
        float xp0=0.f, xp1=0.f, xp2=0.f, xp3=0.f;
        if (upd) {
            const float* xrow = g_xproj + ((size_t)ub*T_ + t)*G_ + jg;
            xp0 = xrow[0*H_]; xp1 = xrow[1*H_];
            xp2 = xrow[2*H_]; xp3 = xrow[3*H_];
        }

        // stage h: 32 x 1024 floats = 8192 float4
        {
            const float4* hsrc = (const float4*)hprev;
            #pragma unroll
            for (int it = 0; it < 16; it++) {
                int e = tid + NTHR*it;
                int r = e >> 8, col4 = e & 255;
                *(float4*)(hs + r*HP + col4*4) = hsrc[r*256 + col4];
            }
        }
        __syncthreads();

        // mainloop: per b, 16 broadcast LDS.128 + 32 fma2
        {
            float* prow = pbuf + w*PB_STRIDE + c*33;
            #pragma unroll 2
            for (int b = 0; b < 32; b++) {
                const ulonglong2* hb =
                    (const ulonglong2*)(hs + b*HP + w*64);
                u64 a0 = 0ULL, a1 = 0ULL;
                #pragma unroll
                for (int m = 0; m < 16; m++) {
                    ulonglong2 hv = hb[m];
                    fma2(a0, wreg[2*m],   hv.x);
                    fma2(a1, wreg[2*m+1], hv.y);
                }
                float2 f0 = unpack2(a0), f1 = unpack2(a1);
                prow[b] = (f0.x + f0.y) + (f1.x + f1.y);
            }
        }
        __syncthreads();

        // reduce 16 warp partials: thread -> (cc, 2 b's)
        {
            int cc = tid >> 4, bb = (tid & 15) * 2;
            float s0 = 0.f, s1 = 0.f;
            #pragma unroll
            for (int ww = 0; ww < 16; ww++) {
                const float* pr = pbuf + ww*PB_STRIDE + cc*33 + bb;
                s0 += pr[0]; s1 += pr[1];
            }
            sp[cc*33 + bb]   = s0;
            sp[cc*33 + bb+1] = s1;
        }
        __syncthreads();

        // gates + cell update
        if (upd) {
            float p0 = sp[(0*8 + uj)*33 + ub] + xp0 + bh0;
            float p1 = sp[(1*8 + uj)*33 + ub] + xp1 + bh1;
            float p2 = sp[(2*8 + uj)*33 + ub] + xp2 + bh2;
            float p3 = sp[(3*8 + uj)*33 + ub] + xp3 + bh3;

            float ig = 1.f / (1.f + __expf(-p0));
            float fg = 1.f / (1.f + __expf(-p1));
            float og = 1.f / (1.f + __expf(-p2));
            float gg = tanhf(p3);
            float cn = cstate*fg + ig*gg;
            cstate = cn;
            float hn = og * tanhf(cn);

            hnext[ub*H_ + jg] = hn;
            out[((size_t)ub*T_ + t)*H_ + jg] = hn;
            if (t == T_ - 1) {
                out[OFF_H + (size_t)ub*H_ + jg] = hn;
                out[OFF_C + (size_t)ub*H_ + jg] = cn;
            }
        }

        if (t + 1 < T_) grid_sync(jb, ++epoch);
    }
}

extern "C" void kernel_launch(void* const* d_in, const int* in_sizes, int n_in,
                              void* d_out, int out_size)
{
    (void)in_sizes; (void)n_in; (void)out_size;
    const float* inputs = (const float*)d_in[0];
    const float* h0     = (const float*)d_in[1];
    const float* c0     = (const float*)d_in[2];
    const float* Wih    = (const float*)d_in[3];
    const float* bih    = (const float*)d_in[4];
    const float* Whh    = (const float*)d_in[5];
    const float* bhh    = (const float*)d_in[6];
    float* out = (float*)d_out;

    cudaFuncSetAttribute(lstm_fused,
                         cudaFuncAttributeMaxDynamicSharedMemorySize,
                         SMEM_BYTES);

    lstm_fused<<<NBLK, NTHR, SMEM_BYTES>>>(
        inputs, h0, c0, Wih, bih, Whh, bhh, out);
}

// round 7
// speedup vs baseline: 1.1864x; 1.1263x over previous
#include <cuda_runtime.h>
#include <cstdint>
#include <cstddef>

#define B_   32
#define T_   512
#define KIN  1024
#define H_   1024
#define G_   4096
#define M_   (B_*T_)
#define JT   8
#define NBLK 128
#define NTHR 1024

__device__ float g_xproj[(size_t)M_ * G_];
__device__ float g_h[2][B_*H_];
__device__ unsigned g_arr[8*32];   // tree barrier, 8 slots 128 B apart

typedef unsigned long long u64;

__device__ __forceinline__ void fma2(u64 &d, u64 a, u64 b){
    asm("fma.rn.f32x2 %0, %1, %2, %0;" : "+l"(d) : "l"(a), "l"(b));
}
__device__ __forceinline__ u64 pack2(float lo, float hi){
    u64 r; asm("mov.b64 %0, {%1,%2};" : "=l"(r) : "f"(lo), "f"(hi)); return r;
}
__device__ __forceinline__ float2 unpack2(u64 v){
    float2 f; asm("mov.b64 {%0,%1}, %2;" : "=f"(f.x), "=f"(f.y) : "l"(v)); return f;
}

// grid sync; 16 arrivals per slot per epoch
__device__ __forceinline__ void grid_sync(int jb, unsigned e)
{
    __syncthreads();
    if (threadIdx.x == 0) {
        __threadfence();
        atomicAdd(&g_arr[(jb & 7) * 32], 1u);
        unsigned tgt = 16u * e;
        volatile unsigned* a = g_arr;
        for (;;) {
            unsigned v0 = a[0*32], v1 = a[1*32], v2 = a[2*32], v3 = a[3*32];
            unsigned v4 = a[4*32], v5 = a[5*32], v6 = a[6*32], v7 = a[7*32];
            if (v0>=tgt && v1>=tgt && v2>=tgt && v3>=tgt &&
                v4>=tgt && v5>=tgt && v6>=tgt && v7>=tgt) break;
        }
        __threadfence();
    }
    __syncthreads();
}

// scan smem layout (floats)
#define HP          1028
#define HS_FLOATS   (32*HP)                  // 131.6 KB
#define PB_WS       (32*17)                  // per-w stride: [c][bl]
#define PB_FLOATS   (32*PB_WS)               // 69.6 KB
#define SP_FLOATS   (32*33)
#define SMEM_BYTES  ((HS_FLOATS + PB_FLOATS + SP_FLOATS)*4)

// xproj aliases: As2 u64[16][258] (33 KB) then Bst float[16][132]
#define XP_AP       258
#define XP_BST_OFF  (16*XP_AP*2)             // float offset

extern __shared__ float smemf[];

__global__ void __launch_bounds__(NTHR, 1) lstm_fused(
    const float* __restrict__ A,
    const float* __restrict__ h0,
    const float* __restrict__ c0,
    const float* __restrict__ Wih,
    const float* __restrict__ bih,
    const float* __restrict__ Whh,
    const float* __restrict__ bhh,
    float* __restrict__ out)
{
    const int tid = threadIdx.x;
    const int jb  = blockIdx.x;

    if (jb == 0 && tid < 8) { g_arr[tid*32] = 0u; __threadfence(); }
    unsigned epoch = 0;

    // ==============================================================
    // Phase A: xproj. 256m x 128n tiles, 16 per block.
    // m-dup A pairs: fma2 packs the n dimension. 8m x 4n per thread.
    // ==============================================================
    {
        u64*   As2 = (u64*)smemf;            // [16][XP_AP]
        float* Bst = smemf + XP_BST_OFF;     // [16][132]

        const int tx   = tid & 31;           // n quad: tx*4
        const int ty   = tid >> 5;           // m oct : ty*8
        const int arow = tid >> 2;           // 0..255
        const int akq  = (tid & 3) * 4;

        for (int i6 = 0; i6 < 16; i6++) {
            int tt = jb*16 + i6;
            int m0 = (tt >> 5) * 256;
            int n0 = (tt & 31) * 128;

            u64 acc[8][2];
            #pragma unroll
            for (int i = 0; i < 8; i++) { acc[i][0]=0ULL; acc[i][1]=0ULL; }

            const float* Ap = A + (size_t)(m0 + arow)*KIN + akq;
            const float* Wp = Wih + (size_t)(n0 + (arow & 127))*KIN + akq;

            for (int kc = 0; kc < KIN; kc += 16) {
                float4 av = *(const float4*)(Ap + kc);
                float4 wv;
                if (tid < 512) wv = *(const float4*)(Wp + kc);

                As2[(akq+0)*XP_AP + arow] = pack2(av.x, av.x);
                As2[(akq+1)*XP_AP + arow] = pack2(av.y, av.y);
                As2[(akq+2)*XP_AP + arow] = pack2(av.z, av.z);
                As2[(akq+3)*XP_AP + arow] = pack2(av.w, av.w);
                if (tid < 512) {
                    Bst[(akq+0)*132 + arow] = wv.x;
                    Bst[(akq+1)*132 + arow] = wv.y;
                    Bst[(akq+2)*132 + arow] = wv.z;
                    Bst[(akq+3)*132 + arow] = wv.w;
                }
                __syncthreads();

                #pragma unroll
                for (int k = 0; k < 16; k++) {
                    const ulonglong2* ap =
                        (const ulonglong2*)&As2[k*XP_AP + ty*8];
                    ulonglong2 bv =
                        *(const ulonglong2*)&Bst[k*132 + tx*4];
                    #pragma unroll
                    for (int mh = 0; mh < 4; mh++) {
                        ulonglong2 a2 = ap[mh];
                        fma2(acc[2*mh  ][0], a2.x, bv.x);
                        fma2(acc[2*mh  ][1], a2.x, bv.y);
                        fma2(acc[2*mh+1][0], a2.y, bv.x);
                        fma2(acc[2*mh+1][1], a2.y, bv.y);
                    }
                }
                __syncthreads();
            }

            float4 bn = *(const float4*)(bih + n0 + tx*4);
            #pragma unroll
            for (int i = 0; i < 8; i++) {
                float2 v0 = unpack2(acc[i][0]);
                float2 v1 = unpack2(acc[i][1]);
                float4 o;
                o.x = v0.x + bn.x; o.y = v0.y + bn.y;
                o.z = v1.x + bn.z; o.w = v1.y + bn.w;
                *(float4*)(g_xproj + (size_t)(m0 + ty*8 + i)*G_
                           + n0 + tx*4) = o;
            }
        }
    }

    grid_sync(jb, ++epoch);

    // ==============================================================
    // Phase B: scan. 32 warps, k-slice 32/warp, b in two halves.
    // ==============================================================
    float* hs   = smemf;
    float* pbuf = smemf + HS_FLOATS;
    float* sp   = pbuf + PB_FLOATS;

    const int w   = tid >> 5;
    const int c   = tid & 31;
    const int n_c = (c >> 3)*H_ + jb*JT + (c & 7);

    u64 wreg[16];
    {
        const float4* wp = (const float4*)(Whh + (size_t)n_c*KIN + w*32);
        #pragma unroll
        for (int m = 0; m < 8; m++) {
            float4 v = wp[m];
            wreg[2*m]   = pack2(v.x, v.y);
            wreg[2*m+1] = pack2(v.z, v.w);
        }
    }

    const bool upd = (tid < 256);
    const int ub = tid >> 3;       // 0..31 (for tid<256)
    const int uj = tid & 7;
    const int jg = jb*JT + uj;
    float cstate = 0.f;
    if (upd) cstate = c0[ub*H_ + jg];

    const size_t OFF_H = (size_t)B_*T_*H_;
    const size_t OFF_C = OFF_H + (size_t)B_*H_;

    for (int t = 0; t < T_; t++) {
        const float* hprev = (t == 0) ? h0 : g_h[t & 1];
        float*       hnext = g_h[(t + 1) & 1];

        // stage full h: 8192 float4, 8 per thread
        {
            const float4* hsrc = (const float4*)hprev;
            #pragma unroll
            for (int it = 0; it < 8; it++) {
                int e = tid + NTHR*it;
                int r = e >> 8, c4 = e & 255;
                *(float4*)(hs + r*HP + c4*4) = hsrc[r*256 + c4];
            }
        }

        // prefetch xproj + bhh (lands during mainloops)
        float xp0=0,xp1=0,xp2=0,xp3=0, bh0=0,bh1=0,bh2=0,bh3=0;
        if (upd) {
            const float* xrow = g_xproj + ((size_t)ub*T_ + t)*G_ + jg;
            xp0 = xrow[0]; xp1 = xrow[H_]; xp2 = xrow[2*H_]; xp3 = xrow[3*H_];
            bh0 = bhh[jg]; bh1 = bhh[H_+jg];
            bh2 = bhh[2*H_+jg]; bh3 = bhh[3*H_+jg];
        }
        __syncthreads();                       // S1: hs ready

        #pragma unroll
        for (int X = 0; X < 2; X++) {
            // update of previous half (X==1: half 0), overlapped w/ mainB
            if (X == 1 && tid < 128) {
                float p0 = sp[(0*8+uj)*33 + ub] + xp0 + bh0;
                float p1 = sp[(1*8+uj)*33 + ub] + xp1 + bh1;
                float p2 = sp[(2*8+uj)*33 + ub] + xp2 + bh2;
                float p3 = sp[(3*8+uj)*33 + ub] + xp3 + bh3;
                float ig = 1.f/(1.f+__expf(-p0));
                float fg = 1.f/(1.f+__expf(-p1));
                float og = 1.f/(1.f+__expf(-p2));
                float gg = tanhf(p3);
                float cn = cstate*fg + ig*gg;
                cstate = cn;
                float hn = og * tanhf(cn);
                hnext[ub*H_ + jg] = hn;
                out[((size_t)ub*T_ + t)*H_ + jg] = hn;
                if (t == T_-1) {
                    out[OFF_H + (size_t)ub*H_ + jg] = hn;
                    out[OFF_C + (size_t)ub*H_ + jg] = cn;
                }
            }

            // mainloop: this half's 16 batches
            {
                float* prow = pbuf + w*PB_WS + c*17;
                #pragma unroll 2
                for (int bl = 0; bl < 16; bl++) {
                    const ulonglong2* hb =
                        (const ulonglong2*)(hs + (X*16+bl)*HP + w*32);
                    u64 a0 = 0ULL, a1 = 0ULL;
                    #pragma unroll
                    for (int m = 0; m < 4; m++) {
                        ulonglong2 h0v = hb[2*m];
                        ulonglong2 h1v = hb[2*m+1];
                        fma2(a0, wreg[4*m+0], h0v.x);
                        fma2(a1, wreg[4*m+1], h0v.y);
                        fma2(a0, wreg[4*m+2], h1v.x);
                        fma2(a1, wreg[4*m+3], h1v.y);
                    }
                    float2 f0 = unpack2(a0), f1 = unpack2(a1);
                    prow[bl] = (f0.x + f0.y) + (f1.x + f1.y);
                }
            }
            __syncthreads();                   // mainloop done

            // reduce 32 partials (warps 0..15)
            if (tid < 512) {
                int cc = tid >> 4, bl = tid & 15;
                float s = 0.f;
                #pragma unroll
                for (int ww = 0; ww < 32; ww++)
                    s += pbuf[ww*PB_WS + cc*17 + bl];
                sp[cc*33 + X*16 + bl] = s;
            }
            __syncthreads();                   // sp[X] ready
        }

        // update half 1 (threads 128..255, ub 16..31)
        if (tid >= 128 && tid < 256) {
            float p0 = sp[(0*8+uj)*33 + ub] + xp0 + bh0;
            float p1 = sp[(1*8+uj)*33 + ub] + xp1 + bh1;
            float p2 = sp[(2*8+uj)*33 + ub] + xp2 + bh2;
            float p3 = sp[(3*8+uj)*33 + ub] + xp3 + bh3;
            float ig = 1.f/(1.f+__expf(-p0));
            float fg = 1.f/(1.f+__expf(-p1));
            float og = 1.f/(1.f+__expf(-p2));
            float gg = tanhf(p3);
            float cn = cstate*fg + ig*gg;
            cstate = cn;
            float hn = og * tanhf(cn);
            hnext[ub*H_ + jg] = hn;
            out[((size_t)ub*T_ + t)*H_ + jg] = hn;
            if (t == T_-1) {
                out[OFF_H + (size_t)ub*H_ + jg] = hn;
                out[OFF_C + (size_t)ub*H_ + jg] = cn;
            }
        }

        if (t + 1 < T_) grid_sync(jb, ++epoch);
    }
}

extern "C" void kernel_launch(void* const* d_in, const int* in_sizes, int n_in,
                              void* d_out, int out_size)
{
    (void)in_sizes; (void)n_in; (void)out_size;
    const float* inputs = (const float*)d_in[0];
    const float* h0     = (const float*)d_in[1];
    const float* c0     = (const float*)d_in[2];
    const float* Wih    = (const float*)d_in[3];
    const float* bih    = (const float*)d_in[4];
    const float* Whh    = (const float*)d_in[5];
    const float* bhh    = (const float*)d_in[6];
    float* out = (float*)d_out;

    cudaFuncSetAttribute(lstm_fused,
                         cudaFuncAttributeMaxDynamicSharedMemorySize,
                         SMEM_BYTES);

    lstm_fused<<<NBLK, NTHR, SMEM_BYTES>>>(
        inputs, h0, c0, Wih, bih, Whh, bhh, out);
}